// round 9
// baseline (speedup 1.0000x reference)
#include <cuda_runtime.h>
#include <cstdint>

#define ASTG 2048            // floats per A stage buffer  [4][4][32][4]
#define BSTG 4096            // floats per B stage buffer  [4][4][64][4]
#define NBUF 3
#define BBASE (NBUF*ASTG)    // B region starts after the 3 A buffers (floats)
#define OSM_ROW 584          // epilogue transpose row stride (64*9+8)
#define SMEM_FLOATS 18688    // max(3*(ASTG+BSTG)=18432, 32*584=18688)
#define SMEM_BYTES (SMEM_FLOATS*4)

#define CSTEP 16384          // +1 channel (floats)

__device__ __forceinline__ uint32_t f2tf32(float f) {
    uint32_t u; asm("cvt.rna.tf32.f32 %0, %1;" : "=r"(u) : "f"(f)); return u;
}
__device__ __forceinline__ void mma_tf32(float& d0, float& d1, float& d2, float& d3,
                                         uint32_t a0, uint32_t a1, uint32_t a2, uint32_t a3,
                                         uint32_t b0, uint32_t b1) {
    asm("mma.sync.aligned.m16n8k8.row.col.f32.tf32.tf32.f32 "
        "{%0,%1,%2,%3},{%4,%5,%6,%7},{%8,%9},{%0,%1,%2,%3};"
        : "+f"(d0), "+f"(d1), "+f"(d2), "+f"(d3)
        : "r"(a0), "r"(a1), "r"(a2), "r"(a3), "r"(b0), "r"(b1));
}
__device__ __forceinline__ void cp16(uint32_t dst, const float* src) {
    asm volatile("cp.async.cg.shared.global [%0], [%1], 16;" :: "r"(dst), "l"(src));
}

__global__ __launch_bounds__(256, 2)
void lc2d_kernel(const float* __restrict__ x,
                 const float* __restrict__ w,
                 const float* __restrict__ bias,
                 float* __restrict__ out) {
    extern __shared__ float sm[];
    const uint32_t smu = (uint32_t)__cvta_generic_to_shared(sm);

    const int tid  = threadIdx.x;
    const int or_  = blockIdx.y;
    const int oct0 = blockIdx.x * 8;
    const int h0   = or_ * 2;
    const int w0   = oct0 * 2;

    // ---- loader mapping ----
    // x: 512 16B-chunks/stage: (c2, row2, b32, j4); thread does c=0,1
    const int xj = tid & 3, xb = (tid >> 2) & 31, xrow = tid >> 7;
    const float* xb0 = x + ((xb * 32) * 128 + h0 + xrow) * 128 + w0 + 4 * xj;
    uint32_t a_dst[2];
#pragma unroll
    for (int cc = 0; cc < 2; ++cc)
        a_dst[cc] = smu + (uint32_t)(((((cc * 2 + xrow) * 4 + xj) * 32 + xb) * 4) * 4);

    // w: 1024 chunks/stage: (c2, row2, f64, j4); thread does 4 (c,row)
    const int wj = tid & 3, wf = tid >> 2;
    const float* wb0 = w + ((wf * 32) * 128 + h0) * 128 + w0 + 4 * wj;
    uint32_t b_dst[2][2];
#pragma unroll
    for (int cc = 0; cc < 2; ++cc)
#pragma unroll
        for (int rw = 0; rw < 2; ++rw)
            b_dst[cc][rw] = smu + (uint32_t)((BBASE + ((((cc * 2 + rw) * 4 + wj) * 64 + wf) * 4)) * 4);

    // ---- mma mapping ----
    const int lane = tid & 31, gp = tid >> 5;   // warp = pooled group
    const int g = lane >> 2, t = lane & 3;

    // A fragment offsets (floats, within an A buffer), for mt=0; +64 for mt=1
    int aoff[4];
#pragma unroll
    for (int r = 0; r < 4; ++r) {
        const int m  = g + (r & 1) * 8;
        const int k  = t + (r >> 1) * 4;
        const int c  = k >> 2, rw = (k >> 1) & 1, cp = k & 1;
        const int col = 2 * gp + cp;
        aoff[r] = (((c * 2 + rw) * 4 + (col >> 2)) * 32 + m) * 4 + (col & 3);
    }
    // B fragment base offsets for k=t and k=t+4 (add nt*32 per n-tile)
    int boff[2];
#pragma unroll
    for (int r2 = 0; r2 < 2; ++r2) {
        const int k  = t + r2 * 4;
        const int c  = k >> 2, rw = (k >> 1) & 1, cp = k & 1;
        const int col = 2 * gp + cp;
        boff[r2] = (((c * 2 + rw) * 4 + (col >> 2)) * 64 + g) * 4 + (col & 3);
    }

    float acc[2][8][4];
#pragma unroll
    for (int mt = 0; mt < 2; ++mt)
#pragma unroll
        for (int nt = 0; nt < 8; ++nt)
#pragma unroll
            for (int r = 0; r < 4; ++r) acc[mt][nt][r] = 0.f;

    // ---- stage issue: 2 channels [2s, 2s+1) into buffer `buf` ----
    auto issue = [&](int s, int buf) {
        const uint32_t ao = (uint32_t)(buf * ASTG * 4);
        const uint32_t bo = (uint32_t)(buf * BSTG * 4);
        const float* xs = xb0 + s * 2 * CSTEP;
        const float* ws = wb0 + s * 2 * CSTEP;
#pragma unroll
        for (int cc = 0; cc < 2; ++cc)
            cp16(a_dst[cc] + ao, xs + cc * CSTEP);
#pragma unroll
        for (int cc = 0; cc < 2; ++cc)
#pragma unroll
            for (int rw = 0; rw < 2; ++rw)
                cp16(b_dst[cc][rw] + bo, ws + cc * CSTEP + rw * 128);
    };

    // ---- prologue: 2 stages in flight ----
    issue(0, 0);
    asm volatile("cp.async.commit_group;");
    issue(1, 1);
    asm volatile("cp.async.commit_group;");

    int buf = 0;
    for (int s = 0; s < 16; ++s) {
        asm volatile("cp.async.wait_group 1;");
        __syncthreads();

        // refill the buffer freed at stage s-1 (all warps past it per barrier)
        if (s + 2 < 16) {
            int nb = buf + 2; if (nb >= NBUF) nb -= NBUF;
            issue(s + 2, nb);
        }
        asm volatile("cp.async.commit_group;");

        const float* Ab = sm + buf * ASTG;
        const float* Bb = sm + BBASE + buf * BSTG;

        uint32_t a[2][4];
#pragma unroll
        for (int mt = 0; mt < 2; ++mt)
#pragma unroll
            for (int r = 0; r < 4; ++r)
                a[mt][r] = f2tf32(Ab[aoff[r] + mt * 64]);

#pragma unroll
        for (int nt = 0; nt < 8; ++nt) {
            const uint32_t b0 = f2tf32(Bb[boff[0] + nt * 32]);
            const uint32_t b1 = f2tf32(Bb[boff[1] + nt * 32]);
            mma_tf32(acc[0][nt][0], acc[0][nt][1], acc[0][nt][2], acc[0][nt][3],
                     a[0][0], a[0][1], a[0][2], a[0][3], b0, b1);
            mma_tf32(acc[1][nt][0], acc[1][nt][1], acc[1][nt][2], acc[1][nt][3],
                     a[1][0], a[1][1], a[1][2], a[1][3], b0, b1);
        }

        if (++buf >= NBUF) buf -= NBUF;
    }
    __syncthreads();   // all compute done before smem reuse

    // ---- epilogue: transpose via smem, bias + relu, coalesced STG ----
    float* OS = sm;
#pragma unroll
    for (int mt = 0; mt < 2; ++mt)
#pragma unroll
        for (int nt = 0; nt < 8; ++nt) {
            const int r0 = mt * 16 + g;
            const int c0 = nt * 8 + 2 * t;
            OS[r0 * OSM_ROW + c0 * 9 + gp]             = acc[mt][nt][0];
            OS[r0 * OSM_ROW + (c0 + 1) * 9 + gp]       = acc[mt][nt][1];
            OS[(r0 + 8) * OSM_ROW + c0 * 9 + gp]       = acc[mt][nt][2];
            OS[(r0 + 8) * OSM_ROW + (c0 + 1) * 9 + gp] = acc[mt][nt][3];
        }
    __syncthreads();

    const float* bb = bias + or_ * 64 + oct0;   // + f*4096
    float* ob       = out + or_ * 64 + oct0;    // + (b*64+f)*4096
#pragma unroll
    for (int i = 0; i < 8; ++i) {
        const int p  = tid + 256 * i;
        const int b_ = p >> 6;
        const int f_ = p & 63;
        const float4 bv0 = *(const float4*)(bb + f_ * 4096);
        const float4 bv1 = *(const float4*)(bb + f_ * 4096 + 4);
        const float* row = OS + b_ * OSM_ROW + f_ * 9;
        float4 o0, o1;
        o0.x = fmaxf(row[0] + bv0.x, 0.f);
        o0.y = fmaxf(row[1] + bv0.y, 0.f);
        o0.z = fmaxf(row[2] + bv0.z, 0.f);
        o0.w = fmaxf(row[3] + bv0.w, 0.f);
        o1.x = fmaxf(row[4] + bv1.x, 0.f);
        o1.y = fmaxf(row[5] + bv1.y, 0.f);
        o1.z = fmaxf(row[6] + bv1.z, 0.f);
        o1.w = fmaxf(row[7] + bv1.w, 0.f);
        float4* dst = (float4*)(ob + (size_t)(b_ * 64 + f_) * 4096);
        dst[0] = o0;
        dst[1] = o1;
    }
}

extern "C" void kernel_launch(void* const* d_in, const int* in_sizes, int n_in,
                              void* d_out, int out_size) {
    const float* x    = (const float*)d_in[0];
    const float* w    = (const float*)d_in[1];
    const float* bias = (const float*)d_in[2];
    float* out        = (float*)d_out;

    cudaFuncSetAttribute(lc2d_kernel,
                         cudaFuncAttributeMaxDynamicSharedMemorySize, SMEM_BYTES);

    dim3 grid(8, 64, 1);
    lc2d_kernel<<<grid, 256, SMEM_BYTES>>>(x, w, bias, out);
}

// round 10
// speedup vs baseline: 1.4995x; 1.4995x over previous
#include <cuda_runtime.h>
#include <cstdint>

#define KA 12                 // k-stride (8 + 4 pad) -> conflict-free fragment LDS
#define AWS 388               // 32*KA + 4  (warp panel stride, A)
#define BWS 772               // 64*KA + 4  (warp panel stride, B)
#define ABUF (8*AWS)          // 3104 floats per A buffer
#define BBUF (8*BWS)          // 6176 floats per B buffer
#define OSM_ROW 581           // 64*9 + 5 (epilogue transpose row stride)
#define SMEM_FLOATS 18592
#define SMEM_BYTES (SMEM_FLOATS*4)

#define PSTEP (16*32*16384)   // +16 in b/f dimension (floats)
#define CSTEP (2*16384)       // +1 stage = +2 channels (floats)

__device__ __forceinline__ uint32_t f2tf32(float f) {
    uint32_t u; asm("cvt.rna.tf32.f32 %0, %1;" : "=r"(u) : "f"(f)); return u;
}
__device__ __forceinline__ void mma_tf32(float& d0, float& d1, float& d2, float& d3,
                                         uint32_t a0, uint32_t a1, uint32_t a2, uint32_t a3,
                                         uint32_t b0, uint32_t b1) {
    asm("mma.sync.aligned.m16n8k8.row.col.f32.tf32.tf32.f32 "
        "{%0,%1,%2,%3},{%4,%5,%6,%7},{%8,%9},{%0,%1,%2,%3};"
        : "+f"(d0), "+f"(d1), "+f"(d2), "+f"(d3)
        : "r"(a0), "r"(a1), "r"(a2), "r"(a3), "r"(b0), "r"(b1));
}
__device__ __forceinline__ void prefL2(const float* p) {
    asm volatile("prefetch.global.L2 [%0];" :: "l"(p));
}

__global__ __launch_bounds__(256, 2)
void lc2d_kernel(const float* __restrict__ x,
                 const float* __restrict__ w,
                 const float* __restrict__ bias,
                 float* __restrict__ out) {
    extern __shared__ float sm[];
    float* AS = sm;                 // [2][warp8][b32][KA]
    float* BS = sm + 2 * ABUF;      // [2][warp8][f64][KA]

    const int tid  = threadIdx.x;
    const int or_  = blockIdx.y;
    const int oct0 = blockIdx.x * 8;
    const int h0   = or_ * 2;
    const int w0   = oct0 * 2;

    // ---- loader mapping: tid -> (colq, row, c_local, b-or-f) ----
    const int colq = tid & 3;            // float4 index along 16 input cols
    const int lrow = (tid >> 2) & 1;     // input row within pooled row
    const int lcl  = (tid >> 3) & 1;     // channel within stage
    const int lb   = tid >> 4;           // 0..15 : b (for x) / f (for W)

    const float* xp = x + ((lb * 32 + lcl) * 128 + h0 + lrow) * 128 + w0 + 4 * colq;
    const float* wp = w + ((lb * 32 + lcl) * 128 + h0 + lrow) * 128 + w0 + 4 * colq;

    // STS offsets: col = 4*colq + e ; wp_e = col>>1 ; cp = col&1 ; k = lcl*4+lrow*2+cp
    int a_off[2][4], b_off[4][4];
#pragma unroll
    for (int e = 0; e < 4; ++e) {
        const int wpe = 2 * colq + (e >> 1);
        const int k   = lcl * 4 + lrow * 2 + (e & 1);
#pragma unroll
        for (int i = 0; i < 2; ++i)
            a_off[i][e] = wpe * AWS + (lb + 16 * i) * KA + k;
#pragma unroll
        for (int i = 0; i < 4; ++i)
            b_off[i][e] = wpe * BWS + (lb + 16 * i) * KA + k;
    }

    // ---- mma mapping ----
    const int lane = tid & 31, wid = tid >> 5;
    const int g = lane >> 2, t = lane & 3;

    int a_ld[2][4];
#pragma unroll
    for (int mt = 0; mt < 2; ++mt) {
        a_ld[mt][0] = wid * AWS + (mt * 16 + g)     * KA + t;
        a_ld[mt][1] = wid * AWS + (mt * 16 + g + 8) * KA + t;
        a_ld[mt][2] = a_ld[mt][0] + 4;
        a_ld[mt][3] = a_ld[mt][1] + 4;
    }

    float acc[2][8][4];
#pragma unroll
    for (int mt = 0; mt < 2; ++mt)
#pragma unroll
        for (int nt = 0; nt < 8; ++nt)
#pragma unroll
            for (int r = 0; r < 4; ++r) acc[mt][nt][r] = 0.f;

    float4 xr[2], wr[4];

    // ---- staging helpers ----
    auto do_ldg = [&](int stage) {
        const int off = stage * CSTEP;
#pragma unroll
        for (int i = 0; i < 2; ++i) xr[i] = *(const float4*)(xp + off + i * PSTEP);
#pragma unroll
        for (int i = 0; i < 4; ++i) wr[i] = *(const float4*)(wp + off + i * PSTEP);
    };
    auto do_pref = [&](int stage) {
        const int off = stage * CSTEP;
#pragma unroll
        for (int i = 0; i < 2; ++i) prefL2(xp + off + i * PSTEP);
#pragma unroll
        for (int i = 0; i < 4; ++i) prefL2(wp + off + i * PSTEP);
    };
    auto do_sts = [&](int buf) {
        float* An = AS + buf * ABUF;
        float* Bn = BS + buf * BBUF;
#pragma unroll
        for (int i = 0; i < 2; ++i) {
            const float v[4] = {xr[i].x, xr[i].y, xr[i].z, xr[i].w};
#pragma unroll
            for (int e = 0; e < 4; ++e)
                An[a_off[i][e]] = __uint_as_float(f2tf32(v[e]));
        }
#pragma unroll
        for (int i = 0; i < 4; ++i) {
            const float v[4] = {wr[i].x, wr[i].y, wr[i].z, wr[i].w};
#pragma unroll
            for (int e = 0; e < 4; ++e)
                Bn[b_off[i][e]] = __uint_as_float(f2tf32(v[e]));
        }
    };

    // ---- prologue: stage0 -> buf0 ; preload stage1 ; prewarm L2 for 2,3 ----
    do_ldg(0);
    do_pref(2);
    do_pref(3);
    do_sts(0);
    do_ldg(1);
    __syncthreads();

    // ---- main loop: LDG distance 2 (consumed next stage), L2-prefetch distance 4 ----
    for (int s = 0; s < 16; ++s) {
        const int buf = s & 1;

        // 1) stage s+1 data (loaded during stage s-1, long landed) -> idle buffer
        if (s + 1 < 16) do_sts(buf ^ 1);
        // 2) issue loads for stage s+2 (should hit L2 thanks to prefetch)
        if (s + 2 < 16) do_ldg(s + 2);
        // 3) warm L2 for stage s+4
        if (s + 4 < 16) do_pref(s + 4);

        // 4) compute on buffer `buf`
        const float* Ap = AS + buf * ABUF;
        const float* Bp = BS + buf * BBUF + wid * BWS;

        uint32_t a[2][4];
#pragma unroll
        for (int mt = 0; mt < 2; ++mt)
#pragma unroll
            for (int r = 0; r < 4; ++r)
                a[mt][r] = __float_as_uint(Ap[a_ld[mt][r]]);

#pragma unroll
        for (int nt = 0; nt < 8; ++nt) {
            const uint32_t b0 = __float_as_uint(Bp[(nt * 8 + g) * KA + t]);
            const uint32_t b1 = __float_as_uint(Bp[(nt * 8 + g) * KA + t + 4]);
            mma_tf32(acc[0][nt][0], acc[0][nt][1], acc[0][nt][2], acc[0][nt][3],
                     a[0][0], a[0][1], a[0][2], a[0][3], b0, b1);
            mma_tf32(acc[1][nt][0], acc[1][nt][1], acc[1][nt][2], acc[1][nt][3],
                     a[1][0], a[1][1], a[1][2], a[1][3], b0, b1);
        }

        __syncthreads();
    }

    // ---- epilogue: transpose through smem, bias + relu, coalesced STG ----
    float* OS = sm;   // safe: last stage ended with __syncthreads()
#pragma unroll
    for (int mt = 0; mt < 2; ++mt)
#pragma unroll
        for (int nt = 0; nt < 8; ++nt) {
            const int r0 = mt * 16 + g;
            const int c0 = nt * 8 + 2 * t;
            OS[r0 * OSM_ROW + c0 * 9 + wid]             = acc[mt][nt][0];
            OS[r0 * OSM_ROW + (c0 + 1) * 9 + wid]       = acc[mt][nt][1];
            OS[(r0 + 8) * OSM_ROW + c0 * 9 + wid]       = acc[mt][nt][2];
            OS[(r0 + 8) * OSM_ROW + (c0 + 1) * 9 + wid] = acc[mt][nt][3];
        }
    __syncthreads();

    const float* bb = bias + or_ * 64 + oct0;   // + f*4096
    float* ob       = out + or_ * 64 + oct0;    // + (b*64+f)*4096
#pragma unroll
    for (int i = 0; i < 8; ++i) {
        const int p  = tid + 256 * i;
        const int b_ = p >> 6;
        const int f_ = p & 63;
        const float4 bv0 = *(const float4*)(bb + f_ * 4096);
        const float4 bv1 = *(const float4*)(bb + f_ * 4096 + 4);
        const float* row = OS + b_ * OSM_ROW + f_ * 9;
        float4 o0, o1;
        o0.x = fmaxf(row[0] + bv0.x, 0.f);
        o0.y = fmaxf(row[1] + bv0.y, 0.f);
        o0.z = fmaxf(row[2] + bv0.z, 0.f);
        o0.w = fmaxf(row[3] + bv0.w, 0.f);
        o1.x = fmaxf(row[4] + bv1.x, 0.f);
        o1.y = fmaxf(row[5] + bv1.y, 0.f);
        o1.z = fmaxf(row[6] + bv1.z, 0.f);
        o1.w = fmaxf(row[7] + bv1.w, 0.f);
        float4* dst = (float4*)(ob + (size_t)(b_ * 64 + f_) * 4096);
        dst[0] = o0;
        dst[1] = o1;
    }
}

extern "C" void kernel_launch(void* const* d_in, const int* in_sizes, int n_in,
                              void* d_out, int out_size) {
    const float* x    = (const float*)d_in[0];
    const float* w    = (const float*)d_in[1];
    const float* bias = (const float*)d_in[2];
    float* out        = (float*)d_out;

    cudaFuncSetAttribute(lc2d_kernel,
                         cudaFuncAttributeMaxDynamicSharedMemorySize, SMEM_BYTES);

    dim3 grid(8, 64, 1);
    lc2d_kernel<<<grid, 256, SMEM_BYTES>>>(x, w, bias, out);
}